// round 11
// baseline (speedup 1.0000x reference)
#include <cuda_runtime.h>
#include <math.h>

#define G 384
#define WORDS 6            // 384 bits / 64
#define NLINES (G * G)     // (x,y) lines
#define TS 16              // tile size (output lines per axis per block)
#define NT (G / TS)        // 24 tiles per axis

typedef unsigned long long u64;

// bit-packed occupancy grid (7 MB; L2-resident)
__device__ u64 g_bits[NLINES * WORDS];

// ---------------------------------------------------------------------------
// K1: gaussian smooth (eager-XLA semantics: plain fp32 mul/add, each op
//     rounded; no FMA contraction) + scatter bits.
//     Index: XLA rewrites x / const -> x * (1/const); fl32(1/fl32(1/384))
//     is exactly 384.0f, so the reference scales by multiplication.
//     Loads staged through smem: 260 points (780 floats) per 256-thread block.
// ---------------------------------------------------------------------------
__device__ __forceinline__ int reflect_idx(int j, int n) {
    // numpy 'symmetric' padding: -1->0, -2->1, n->n-1, n+1->n-2
    if (j < 0)  return -j - 1;
    if (j >= n) return 2 * n - 1 - j;
    return j;
}

// 5-term chain, left-associated, every op individually rounded (no FMA)
__device__ __forceinline__ float chain5(float u0, float t0, float u1, float t1,
                                        float u2, float t2, float u3, float t3,
                                        float u4, float t4) {
    float s = __fmul_rn(u0, t0);
    s = __fadd_rn(s, __fmul_rn(u1, t1));
    s = __fadd_rn(s, __fmul_rn(u2, t2));
    s = __fadd_rn(s, __fmul_rn(u3, t3));
    s = __fadd_rn(s, __fmul_rn(u4, t4));
    return s;
}

__global__ void __launch_bounds__(256) smooth_scatter_kernel(
        const float* __restrict__ pts, int n,
        float w0, float w1, float w2) {
    __shared__ float sp[780];          // points [B-2, B+258) x 3 comps
    int B = blockIdx.x * 256;
    int t = threadIdx.x;

    // stage: coalesced in the interior; reflect only at array ends
    for (int i = t; i < 780; i += 256) {
        int q = B - 2 + i / 3;         // point index
        int c = i - (i / 3) * 3;       // component
        int r = reflect_idx(q, n);
        sp[i] = __ldg(&pts[r * 3 + c]);
    }
    __syncthreads();

    int j = B + t;
    if (j >= n) return;

    float y[3];
#pragma unroll
    for (int c = 0; c < 3; c++) {
        // sp offsets: jm2 -> 3t, jm1 -> 3t+3, j -> 3t+6, jp1 -> 3t+9, jp2 -> 3t+12
        y[c] = chain5(w0, sp[3 * t + c],      w1, sp[3 * t + 3 + c],
                      w2, sp[3 * t + 6 + c],  w1, sp[3 * t + 9 + c],
                      w0, sp[3 * t + 12 + c]);
    }

    // axis-1 smoothing, symmetric pad of [y0,y1,y2] -> [y1,y0 | y0,y1,y2 | y2,y1]
    float z0 = chain5(w0, y[1], w1, y[0], w2, y[0], w1, y[1], w0, y[2]);
    float z1 = chain5(w0, y[0], w1, y[0], w2, y[1], w1, y[2], w0, y[2]);
    float z2 = chain5(w0, y[0], w1, y[1], w2, y[2], w1, y[2], w0, y[1]);

    int ix = (int)floorf(__fmul_rn(z0, 384.0f));
    int iy = (int)floorf(__fmul_rn(z1, 384.0f));
    int iz = (int)floorf(__fmul_rn(z2, 384.0f));
    ix = min(max(ix, 0), G - 1);
    iy = min(max(iy, 0), G - 1);
    iz = min(max(iz, 0), G - 1);

    atomicOr(&g_bits[(ix * G + iy) * WORDS + (iz >> 6)], 1ull << (iz & 63));
}

// ---------------------------------------------------------------------------
// K2: fused 3x3x3 closing (dilate -> erode) + fp32 expand, tiled in smem.
// Per block: 16x16 output lines. Halo: bits 20x20, dilated 18x18.
// OR/AND commute with the z bit-shifts, so each stage is:
//   combine 9 neighbor lines wordwise, then one z-shift triple.
// ---------------------------------------------------------------------------
__global__ void __launch_bounds__(256) close_expand_kernel(float* __restrict__ out) {
    __shared__ u64 sb[20][20][WORDS];   // bits halo      (19200 B)
    __shared__ u64 sd[18][18][WORDS];   // dilated        (15552 B)
    __shared__ u64 se[TS][TS][WORDS];   // eroded         (12288 B)

    int t = threadIdx.x;
    int X0 = (int)blockIdx.x * TS;      // tile origin x
    int Y0 = (int)blockIdx.y * TS;      // tile origin y

    // ---- phase 1: load 20x20 line halo of g_bits (zero OOB) ----
    for (int w = t; w < 20 * 20 * WORDS; w += 256) {
        int l  = w / WORDS;
        int k  = w - l * WORDS;
        int xx = l / 20;
        int yy = l - xx * 20;
        int ax = X0 - 2 + xx;
        int ay = Y0 - 2 + yy;
        u64 v = 0ull;
        if (ax >= 0 && ax < G && ay >= 0 && ay < G)
            v = g_bits[(ax * G + ay) * WORDS + k];
        sb[xx][yy][k] = v;
    }
    __syncthreads();

    // ---- phase 2: dilation for 18x18 interior ----
    for (int li = t; li < 18 * 18; li += 256) {
        int xx = li / 18;
        int yy = li - xx * 18;
        u64 o[WORDS];
#pragma unroll
        for (int k = 0; k < WORDS; k++) o[k] = 0ull;
#pragma unroll
        for (int dx = 0; dx < 3; dx++)
#pragma unroll
            for (int dy = 0; dy < 3; dy++) {
#pragma unroll
                for (int k = 0; k < WORDS; k++) o[k] |= sb[xx + dx][yy + dy][k];
            }
#pragma unroll
        for (int k = 0; k < WORDS; k++) {
            u64 prev = (k > 0)         ? o[k - 1] : 0ull;
            u64 nxt  = (k < WORDS - 1) ? o[k + 1] : 0ull;
            u64 sl = (o[k] << 1) | (prev >> 63);
            u64 sr = (o[k] >> 1) | (nxt << 63);
            sd[xx][yy][k] = o[k] | sl | sr;
        }
    }
    __syncthreads();

    // ---- phase 3: erosion for 16x16 core (zero-pad: borders -> 0) ----
    {
        int xx = t / TS;        // 0..15
        int yy = t - xx * TS;
        int ax = X0 + xx;
        int ay = Y0 + yy;
        if (ax == 0 || ax == G - 1 || ay == 0 || ay == G - 1) {
#pragma unroll
            for (int k = 0; k < WORDS; k++) se[xx][yy][k] = 0ull;
        } else {
            u64 a[WORDS];
#pragma unroll
            for (int k = 0; k < WORDS; k++) a[k] = ~0ull;
#pragma unroll
            for (int dx = 0; dx < 3; dx++)
#pragma unroll
                for (int dy = 0; dy < 3; dy++) {
#pragma unroll
                    for (int k = 0; k < WORDS; k++) a[k] &= sd[xx + dx][yy + dy][k];
                }
#pragma unroll
            for (int k = 0; k < WORDS; k++) {
                u64 prev = (k > 0)         ? a[k - 1] : 0ull;
                u64 nxt  = (k < WORDS - 1) ? a[k + 1] : 0ull;
                u64 sl = (a[k] << 1) | (prev >> 63);
                u64 sr = (a[k] >> 1) | (nxt << 63);
                se[xx][yy][k] = a[k] & sl & sr;
            }
        }
    }
    __syncthreads();

    // ---- phase 4: expand to fp32, coalesced uint4 streaming stores.
    // 0.0f/1.0f synthesized integerly: bit * 0x3F800000 (one IMAD, no I2F).
    const unsigned int* se32 = (const unsigned int*)se;  // [line][12] u32 words
    uint4* __restrict__ out4 = (uint4*)out;
#pragma unroll 4
    for (int it = 0; it < (TS * TS * (G / 4)) / 256; it++) {
        int flat = t + it * 256;           // [line_local (0..255)][q (0..95)]
        int ll = flat / (G / 4);
        int q  = flat - ll * (G / 4);
        unsigned int w = se32[ll * (WORDS * 2) + (q >> 3)];
        int sh = (q & 7) * 4;
        uint4 v;
        v.x = ((w >> (sh + 0)) & 1u) * 0x3F800000u;
        v.y = ((w >> (sh + 1)) & 1u) * 0x3F800000u;
        v.z = ((w >> (sh + 2)) & 1u) * 0x3F800000u;
        v.w = ((w >> (sh + 3)) & 1u) * 0x3F800000u;
        int xx = ll / TS;
        int yy = ll - xx * TS;
        int line = (X0 + xx) * G + (Y0 + yy);
        __stcs(&out4[line * (G / 4) + q], v);
    }
}

// ---------------------------------------------------------------------------
// launch
// ---------------------------------------------------------------------------
extern "C" void kernel_launch(void* const* d_in, const int* in_sizes, int n_in,
                              void* d_out, int out_size) {
    const float* pts = (const float*)d_in[0];
    int n = in_sizes[0] / 3;
    float* out = (float*)d_out;

    // gaussian weights (fp32, numpy semantics): [e^-8, e^-2, 1, e^-2, e^-8]/sum
    float e8 = (float)exp(-8.0);
    float e2 = (float)exp(-2.0);
    float s = e8;
    s = s + e2;
    s = s + 1.0f;
    s = s + e2;
    s = s + e8;
    float w0 = e8 / s;
    float w1 = e2 / s;
    float w2 = 1.0f / s;

    // clear via memset node (graph-capturable, driver-optimized path)
    void* bits_ptr = nullptr;
    cudaGetSymbolAddress(&bits_ptr, g_bits);
    cudaMemsetAsync(bits_ptr, 0, (size_t)NLINES * WORDS * sizeof(u64));

    smooth_scatter_kernel<<<(n + 255) / 256, 256>>>(pts, n, w0, w1, w2);
    dim3 grid(NT, NT);
    close_expand_kernel<<<grid, 256>>>(out);
}

// round 15
// speedup vs baseline: 1.1034x; 1.1034x over previous
#include <cuda_runtime.h>
#include <math.h>

#define G 384
#define WORDS 6            // 384 bits / 64
#define NLINES (G * G)     // (x,y) lines
#define TS 16              // tile size (output lines per axis per block)
#define NT (G / TS)        // 24 tiles per axis

typedef unsigned long long u64;

// bit-packed occupancy grid (7 MB; L2-resident)
__device__ u64 g_bits[NLINES * WORDS];

// ---------------------------------------------------------------------------
// K0: clear the bit grid. 16B stores, 2 per thread.
// ---------------------------------------------------------------------------
__global__ void clear_bits_kernel() {
    ulonglong2* p = reinterpret_cast<ulonglong2*>(g_bits);
    int i = blockIdx.x * (512 * 2) + threadIdx.x;
    ulonglong2 z = make_ulonglong2(0ull, 0ull);
    p[i] = z;
    p[i + 512] = z;
}

// ---------------------------------------------------------------------------
// K1: gaussian smooth (eager-XLA semantics: plain fp32 mul/add, each op
//     rounded; no FMA contraction) + scatter bits.
//     Index: XLA rewrites x / const -> x * (1/const); fl32(1/fl32(1/384))
//     is exactly 384.0f, so the reference scales by multiplication.
// ---------------------------------------------------------------------------
__device__ __forceinline__ int reflect_idx(int j, int n) {
    // numpy 'symmetric' padding: -1->0, -2->1, n->n-1, n+1->n-2
    if (j < 0)  return -j - 1;
    if (j >= n) return 2 * n - 1 - j;
    return j;
}

// 5-term chain, left-associated, every op individually rounded (no FMA)
__device__ __forceinline__ float chain5(float u0, float t0, float u1, float t1,
                                        float u2, float t2, float u3, float t3,
                                        float u4, float t4) {
    float s = __fmul_rn(u0, t0);
    s = __fadd_rn(s, __fmul_rn(u1, t1));
    s = __fadd_rn(s, __fmul_rn(u2, t2));
    s = __fadd_rn(s, __fmul_rn(u3, t3));
    s = __fadd_rn(s, __fmul_rn(u4, t4));
    return s;
}

__global__ void smooth_scatter_kernel(const float* __restrict__ pts, int n,
                                      float w0, float w1, float w2) {
    int j = blockIdx.x * blockDim.x + threadIdx.x;
    if (j >= n) return;

    int jm2 = reflect_idx(j - 2, n);
    int jm1 = reflect_idx(j - 1, n);
    int jp1 = reflect_idx(j + 1, n);
    int jp2 = reflect_idx(j + 2, n);

    float y[3];
#pragma unroll
    for (int c = 0; c < 3; c++) {
        float a = __ldg(&pts[jm2 * 3 + c]);
        float b = __ldg(&pts[jm1 * 3 + c]);
        float d = __ldg(&pts[j   * 3 + c]);
        float e = __ldg(&pts[jp1 * 3 + c]);
        float f = __ldg(&pts[jp2 * 3 + c]);
        y[c] = chain5(w0, a, w1, b, w2, d, w1, e, w0, f);
    }

    // axis-1 smoothing, symmetric pad of [y0,y1,y2] -> [y1,y0 | y0,y1,y2 | y2,y1]
    float z0 = chain5(w0, y[1], w1, y[0], w2, y[0], w1, y[1], w0, y[2]);
    float z1 = chain5(w0, y[0], w1, y[0], w2, y[1], w1, y[2], w0, y[2]);
    float z2 = chain5(w0, y[0], w1, y[1], w2, y[2], w1, y[2], w0, y[1]);

    int ix = (int)floorf(__fmul_rn(z0, 384.0f));
    int iy = (int)floorf(__fmul_rn(z1, 384.0f));
    int iz = (int)floorf(__fmul_rn(z2, 384.0f));
    ix = min(max(ix, 0), G - 1);
    iy = min(max(iy, 0), G - 1);
    iz = min(max(iz, 0), G - 1);

    atomicOr(&g_bits[(ix * G + iy) * WORDS + (iz >> 6)], 1ull << (iz & 63));
}

// ---------------------------------------------------------------------------
// K2: fused 3x3x3 closing (dilate -> erode) + fp32 expand, tiled in smem.
// 512 threads/block for ~full warp occupancy (single wave of 576 blocks).
// smem pooled: se aliases sb (dead after phase-2 barrier) -> 34.8 KB.
// ---------------------------------------------------------------------------
#define SB_WORDS (20 * 20 * WORDS)   // 2400
#define SD_WORDS (18 * 18 * WORDS)   // 1944

__global__ void __launch_bounds__(512, 3) close_expand_kernel(float* __restrict__ out) {
    __shared__ u64 pool[SB_WORDS + SD_WORDS];   // 34752 B
    u64* sb = pool;                 // [20][20][WORDS]
    u64* sd = pool + SB_WORDS;      // [18][18][WORDS]
    u64* se = pool;                 // [16][16][WORDS], aliases sb

    int t = threadIdx.x;
    int X0 = (int)blockIdx.x * TS;      // tile origin x
    int Y0 = (int)blockIdx.y * TS;      // tile origin y

    // ---- phase 1: load 20x20 line halo of g_bits (zero OOB) ----
    for (int w = t; w < SB_WORDS; w += 512) {
        int l  = w / WORDS;
        int k  = w - l * WORDS;
        int xx = l / 20;
        int yy = l - xx * 20;
        int ax = X0 - 2 + xx;
        int ay = Y0 - 2 + yy;
        u64 v = 0ull;
        if (ax >= 0 && ax < G && ay >= 0 && ay < G)
            v = g_bits[(ax * G + ay) * WORDS + k];
        sb[(xx * 20 + yy) * WORDS + k] = v;
    }
    __syncthreads();

    // ---- phase 2: dilation for 18x18 interior ----
    for (int li = t; li < 18 * 18; li += 512) {
        int xx = li / 18;
        int yy = li - xx * 18;
        u64 o[WORDS];
#pragma unroll
        for (int k = 0; k < WORDS; k++) o[k] = 0ull;
#pragma unroll
        for (int dx = 0; dx < 3; dx++)
#pragma unroll
            for (int dy = 0; dy < 3; dy++) {
                const u64* L = &sb[((xx + dx) * 20 + (yy + dy)) * WORDS];
#pragma unroll
                for (int k = 0; k < WORDS; k++) o[k] |= L[k];
            }
        u64* D = &sd[(xx * 18 + yy) * WORDS];
#pragma unroll
        for (int k = 0; k < WORDS; k++) {
            u64 prev = (k > 0)         ? o[k - 1] : 0ull;
            u64 nxt  = (k < WORDS - 1) ? o[k + 1] : 0ull;
            u64 sl = (o[k] << 1) | (prev >> 63);
            u64 sr = (o[k] >> 1) | (nxt << 63);
            D[k] = o[k] | sl | sr;
        }
    }
    __syncthreads();

    // ---- phase 3: erosion for 16x16 core (zero-pad: borders -> 0) ----
    if (t < TS * TS) {
        int xx = t / TS;        // 0..15
        int yy = t - xx * TS;
        int ax = X0 + xx;
        int ay = Y0 + yy;
        u64* E = &se[(xx * TS + yy) * WORDS];
        if (ax == 0 || ax == G - 1 || ay == 0 || ay == G - 1) {
#pragma unroll
            for (int k = 0; k < WORDS; k++) E[k] = 0ull;
        } else {
            u64 a[WORDS];
#pragma unroll
            for (int k = 0; k < WORDS; k++) a[k] = ~0ull;
#pragma unroll
            for (int dx = 0; dx < 3; dx++)
#pragma unroll
                for (int dy = 0; dy < 3; dy++) {
                    const u64* L = &sd[((xx + dx) * 18 + (yy + dy)) * WORDS];
#pragma unroll
                    for (int k = 0; k < WORDS; k++) a[k] &= L[k];
                }
#pragma unroll
            for (int k = 0; k < WORDS; k++) {
                u64 prev = (k > 0)         ? a[k - 1] : 0ull;
                u64 nxt  = (k < WORDS - 1) ? a[k + 1] : 0ull;
                u64 sl = (a[k] << 1) | (prev >> 63);
                u64 sr = (a[k] >> 1) | (nxt << 63);
                E[k] = a[k] & sl & sr;
            }
        }
    }
    __syncthreads();

    // ---- phase 4: expand to fp32, coalesced uint4 streaming stores.
    // 0.0f/1.0f synthesized integerly: bit * 0x3F800000 (one IMAD, no I2F).
    const unsigned int* se32 = (const unsigned int*)se;  // [line][12] u32 words
    uint4* __restrict__ out4 = (uint4*)out;
#pragma unroll 4
    for (int it = 0; it < (TS * TS * (G / 4)) / 512; it++) {
        int flat = t + it * 512;           // [line_local (0..255)][q (0..95)]
        int ll = flat / (G / 4);
        int q  = flat - ll * (G / 4);
        unsigned int w = se32[ll * (WORDS * 2) + (q >> 3)];
        int sh = (q & 7) * 4;
        uint4 v;
        v.x = ((w >> (sh + 0)) & 1u) * 0x3F800000u;
        v.y = ((w >> (sh + 1)) & 1u) * 0x3F800000u;
        v.z = ((w >> (sh + 2)) & 1u) * 0x3F800000u;
        v.w = ((w >> (sh + 3)) & 1u) * 0x3F800000u;
        int xx = ll / TS;
        int yy = ll - xx * TS;
        int line = (X0 + xx) * G + (Y0 + yy);
        __stcs(&out4[line * (G / 4) + q], v);
    }
}

// ---------------------------------------------------------------------------
// launch
// ---------------------------------------------------------------------------
extern "C" void kernel_launch(void* const* d_in, const int* in_sizes, int n_in,
                              void* d_out, int out_size) {
    const float* pts = (const float*)d_in[0];
    int n = in_sizes[0] / 3;
    float* out = (float*)d_out;

    // gaussian weights (fp32, numpy semantics): [e^-8, e^-2, 1, e^-2, e^-8]/sum
    float e8 = (float)exp(-8.0);
    float e2 = (float)exp(-2.0);
    float s = e8;
    s = s + e2;
    s = s + 1.0f;
    s = s + e2;
    s = s + e8;
    float w0 = e8 / s;
    float w1 = e2 / s;
    float w2 = 1.0f / s;

    clear_bits_kernel<<<432, 512>>>();
    smooth_scatter_kernel<<<(n + 255) / 256, 256>>>(pts, n, w0, w1, w2);
    dim3 grid(NT, NT);
    close_expand_kernel<<<grid, 512>>>(out);
}